// round 8
// baseline (speedup 1.0000x reference)
#include <cuda_runtime.h>
#include <math.h>

// Problem constants
#define BB   8
#define CC   256
#define HH   64
#define WW   64
#define NN   4096          // H*W
#define MQKV 768           // 3*C
#define NUMEL (BB*CC*NN)   // 8388608

__constant__ int c_dil[4] = {1, 2, 3, 4};
constexpr float SCALE_F = 0.17677669529663687f; // 32^-0.5
constexpr float EPS_F   = 1e-5f;

// Scratch (static device globals — no runtime allocation).
// g_xn is reused: first holds LN output (input to QKV GEMM), then the
// attention output (input to proj GEMM). Kernels serialize on the stream.
__device__ float g_xn [BB * CC * NN];      // LN output / attn output
__device__ float g_qkv[BB * 3 * CC * NN];  // qkv, [b][o][n], o in [0,768)
__device__ float g_div[BB * CC * NN];      // residual-out [b][c][n]

// ---------------------------------------------------------------------------
// Kernel 1: sub = vi - ir ; LayerNorm over C per (b, n). Writes g_xn.
// block (32, 8): 32 pixels per block, 8 channel-lanes each handling 32 chans.
// ---------------------------------------------------------------------------
__global__ __launch_bounds__(256)
void k_subln(const float* __restrict__ vi, const float* __restrict__ ir,
             const float* __restrict__ ln_g, const float* __restrict__ ln_b)
{
    const int b  = blockIdx.y;
    const int n  = blockIdx.x * 32 + threadIdx.x;
    const int tx = threadIdx.x, ty = threadIdx.y;
    const size_t base = (size_t)b * CC * NN + n;

    __shared__ float s_sum[8][32];
    __shared__ float s_sq [8][32];
    __shared__ float s_mean[32];
    __shared__ float s_rstd[32];

    float vals[32];
    float s = 0.f, s2 = 0.f;
#pragma unroll
    for (int u = 0; u < 32; ++u) {
        const int c = ty + u * 8;
        const float v = vi[base + (size_t)c * NN] - ir[base + (size_t)c * NN];
        vals[u] = v; s += v; s2 += v * v;
    }
    s_sum[ty][tx] = s; s_sq[ty][tx] = s2;
    __syncthreads();
    if (ty == 0) {
        float tot = 0.f, tot2 = 0.f;
#pragma unroll
        for (int u = 0; u < 8; ++u) { tot += s_sum[u][tx]; tot2 += s_sq[u][tx]; }
        const float mean = tot * (1.0f / CC);
        const float var  = tot2 * (1.0f / CC) - mean * mean;
        s_mean[tx] = mean;
        s_rstd[tx] = rsqrtf(var + EPS_F);
    }
    __syncthreads();
    const float mean = s_mean[tx], rstd = s_rstd[tx];
#pragma unroll
    for (int u = 0; u < 32; ++u) {
        const int c = ty + u * 8;
        g_xn[base + (size_t)c * NN] = (vals[u] - mean) * rstd * ln_g[c] + ln_b[c];
    }
}

// ---------------------------------------------------------------------------
// Tiled fp32 GEMM: C[b][m][n] = sum_c A[m][c] * B[b][c][n]  (K = 256 fixed)
// BM=BN=128, BK=8, 256 threads, 8x8 micro-tile.
// MODE 0: A=w_qkv (M=768), B=g_xn,  C=g_qkv
// MODE 1: A=proj_w (M=256), B=g_xn (attn out), C=g_div,
//         epilogue += bias + (vi - ir)
// ---------------------------------------------------------------------------
template <int MODE>
__global__ __launch_bounds__(256)
void k_gemm(const float* __restrict__ A,
            const float* __restrict__ bias,
            const float* __restrict__ vi,
            const float* __restrict__ ir)
{
    const int b  = blockIdx.z;
    const int m0 = blockIdx.y * 128;
    const int n0 = blockIdx.x * 128;

    const float* __restrict__ Bp = g_xn + (size_t)b * CC * NN;
    float* __restrict__ Cp = (MODE == 0 ? g_qkv + (size_t)b * MQKV * NN
                                        : g_div + (size_t)b * CC * NN);

    // As transposed [k][m], padded stride 132 (mult of 4 -> 16B-aligned rows)
    __shared__ __align__(16) float As[8][132];
    __shared__ __align__(16) float Bs[8][132];

    const int t  = threadIdx.x;
    const int tx = t & 15, ty = t >> 4;        // 16x16 thread grid

    // A load: thread -> row (t>>1) of the 128-row tile, k-offset (t&1)*4
    const int am = t >> 1;
    const int ak = (t & 1) * 4;
    // B load: thread -> k row (t>>5), n-offset (t&31)*4
    const int bk = t >> 5;
    const int bn = (t & 31) * 4;

    const float* Aptr = A + (size_t)(m0 + am) * 256 + ak;
    const float* Bptr = Bp + (size_t)bk * NN + n0 + bn;

    float acc[8][8] = {};

    for (int k0 = 0; k0 < 256; k0 += 8) {
        const float4 a4 = *reinterpret_cast<const float4*>(Aptr + k0);
        As[ak + 0][am] = a4.x; As[ak + 1][am] = a4.y;
        As[ak + 2][am] = a4.z; As[ak + 3][am] = a4.w;
        *reinterpret_cast<float4*>(&Bs[bk][bn]) =
            *reinterpret_cast<const float4*>(Bptr + (size_t)k0 * NN);
        __syncthreads();
#pragma unroll
        for (int k = 0; k < 8; ++k) {
            float a_[8], b_[8];
            *reinterpret_cast<float4*>(&a_[0]) = *reinterpret_cast<const float4*>(&As[k][ty * 8]);
            *reinterpret_cast<float4*>(&a_[4]) = *reinterpret_cast<const float4*>(&As[k][ty * 8 + 4]);
            *reinterpret_cast<float4*>(&b_[0]) = *reinterpret_cast<const float4*>(&Bs[k][tx * 8]);
            *reinterpret_cast<float4*>(&b_[4]) = *reinterpret_cast<const float4*>(&Bs[k][tx * 8 + 4]);
#pragma unroll
            for (int i = 0; i < 8; ++i)
#pragma unroll
                for (int j = 0; j < 8; ++j)
                    acc[i][j] += a_[i] * b_[j];
        }
        __syncthreads();
    }

#pragma unroll
    for (int i = 0; i < 8; ++i) {
        const int m = m0 + ty * 8 + i;
        const int n = n0 + tx * 8;
        float4 v0 = make_float4(acc[i][0], acc[i][1], acc[i][2], acc[i][3]);
        float4 v1 = make_float4(acc[i][4], acc[i][5], acc[i][6], acc[i][7]);
        if (MODE == 1) {
            const size_t idx = (size_t)b * CC * NN + (size_t)m * NN + n;
            const float4 rv0 = *reinterpret_cast<const float4*>(vi + idx);
            const float4 ri0 = *reinterpret_cast<const float4*>(ir + idx);
            const float4 rv1 = *reinterpret_cast<const float4*>(vi + idx + 4);
            const float4 ri1 = *reinterpret_cast<const float4*>(ir + idx + 4);
            const float bb = bias[m];
            v0.x += bb + rv0.x - ri0.x; v0.y += bb + rv0.y - ri0.y;
            v0.z += bb + rv0.z - ri0.z; v0.w += bb + rv0.w - ri0.w;
            v1.x += bb + rv1.x - ri1.x; v1.y += bb + rv1.y - ri1.y;
            v1.z += bb + rv1.z - ri1.z; v1.w += bb + rv1.w - ri1.w;
        }
        *reinterpret_cast<float4*>(&Cp[(size_t)m * NN + n])     = v0;
        *reinterpret_cast<float4*>(&Cp[(size_t)m * NN + n + 4]) = v1;
    }
}

// ---------------------------------------------------------------------------
// Kernel 3: dilated local attention. One thread per (b, global head, pixel).
// grid (N/128, 8 heads, B), block 128. Writes attn output into g_xn
// (LN output is dead after the QKV GEMM).
// ---------------------------------------------------------------------------
__global__ __launch_bounds__(128)
void k_attn()
{
    const int b  = blockIdx.z;
    const int hg = blockIdx.y;               // global head 0..7
    const int n  = blockIdx.x * 128 + threadIdx.x;
    const int g  = hg >> 1;                  // dilation group
    const int dil = c_dil[g];
    const int qc = g * 64 + (hg & 1) * 32;   // channel base within 256

    const float* __restrict__ base = g_qkv + (size_t)b * MQKV * NN;
    const float* __restrict__ qp = base + (size_t)qc * NN;
    const float* __restrict__ kp = base + (size_t)(256 + qc) * NN;
    const float* __restrict__ vp = base + (size_t)(512 + qc) * NN;

    const int yy = n >> 6, xx = n & 63;

    float q[32];
#pragma unroll
    for (int c = 0; c < 32; ++c) q[c] = qp[(size_t)c * NN + n];

    float logit[9];
    float mx = -1e30f;
#pragma unroll
    for (int t = 0; t < 9; ++t) {
        const int py = yy + (t / 3 - 1) * dil;
        const int px = xx + (t % 3 - 1) * dil;
        float s = 0.f;
        if ((unsigned)py < 64u && (unsigned)px < 64u) {
            const float* kcol = kp + py * 64 + px;
#pragma unroll
            for (int c = 0; c < 32; ++c) s += q[c] * kcol[(size_t)c * NN];
        }
        s *= SCALE_F;           // zero-padded taps give exactly 0 (matches Unfold)
        logit[t] = s;
        mx = fmaxf(mx, s);
    }
    float den = 0.f;
#pragma unroll
    for (int t = 0; t < 9; ++t) { logit[t] = expf(logit[t] - mx); den += logit[t]; }
    const float inv = 1.0f / den;

    float acc[32] = {};
#pragma unroll
    for (int t = 0; t < 9; ++t) {
        const int py = yy + (t / 3 - 1) * dil;
        const int px = xx + (t % 3 - 1) * dil;
        if ((unsigned)py < 64u && (unsigned)px < 64u) {
            const float p = logit[t] * inv;
            const float* vcol = vp + py * 64 + px;
#pragma unroll
            for (int c = 0; c < 32; ++c) acc[c] += p * vcol[(size_t)c * NN];
        }
    }
    float* __restrict__ yp = g_xn + (size_t)b * CC * NN + (size_t)qc * NN + n;
#pragma unroll
    for (int c = 0; c < 32; ++c) yp[(size_t)c * NN] = acc[c];
}

// ---------------------------------------------------------------------------
// Kernel 5: per-(b,c) 64x64 @ 64x64 matmul: o = vi[b,c] @ div[b,c].
// One block per (b*256 + c). Writes output once or twice (dup).
// ---------------------------------------------------------------------------
__global__ __launch_bounds__(256)
void k_final(const float* __restrict__ vi, float* __restrict__ out, int dup)
{
    const int bc = blockIdx.x;
    const float* __restrict__ Ap = vi    + (size_t)bc * 4096;
    const float* __restrict__ Bp = g_div + (size_t)bc * 4096;

    __shared__ __align__(16) float Asm[64][68];  // transposed: Asm[k][i] = A[i][k]
    __shared__ __align__(16) float Bsm[64][64];

    const int t  = threadIdx.x;
    const int tx = t & 15, ty = t >> 4;

#pragma unroll
    for (int it = 0; it < 4; ++it) {
        const int e  = t + 256 * it;
        const int r  = e >> 4;
        const int c4 = (e & 15) * 4;
        const float4 a4 = *reinterpret_cast<const float4*>(Ap + r * 64 + c4);
        Asm[c4 + 0][r] = a4.x; Asm[c4 + 1][r] = a4.y;
        Asm[c4 + 2][r] = a4.z; Asm[c4 + 3][r] = a4.w;
        *reinterpret_cast<float4*>(&Bsm[r][c4]) =
            *reinterpret_cast<const float4*>(Bp + r * 64 + c4);
    }
    __syncthreads();

    float acc[4][4] = {};
#pragma unroll
    for (int k = 0; k < 64; ++k) {
        float a_[4], b_[4];
#pragma unroll
        for (int i = 0; i < 4; ++i) a_[i] = Asm[k][ty * 4 + i];
#pragma unroll
        for (int j = 0; j < 4; ++j) b_[j] = Bsm[k][tx * 4 + j];
#pragma unroll
        for (int i = 0; i < 4; ++i)
#pragma unroll
            for (int j = 0; j < 4; ++j)
                acc[i][j] += a_[i] * b_[j];
    }

#pragma unroll
    for (int i = 0; i < 4; ++i) {
        const size_t idx = (size_t)bc * 4096 + (size_t)(ty * 4 + i) * 64 + tx * 4;
        const float4 v = make_float4(acc[i][0], acc[i][1], acc[i][2], acc[i][3]);
        *reinterpret_cast<float4*>(out + idx) = v;
        if (dup) *reinterpret_cast<float4*>(out + (size_t)NUMEL + idx) = v;
    }
}

// ---------------------------------------------------------------------------
extern "C" void kernel_launch(void* const* d_in, const int* in_sizes, int n_in,
                              void* d_out, int out_size)
{
    const float* vi     = (const float*)d_in[0];
    const float* ir     = (const float*)d_in[1];
    const float* w_qkv  = (const float*)d_in[2];
    const float* proj_w = (const float*)d_in[3];
    const float* proj_b = (const float*)d_in[4];
    const float* ln_g   = (const float*)d_in[5];
    const float* ln_b   = (const float*)d_in[6];
    float* out = (float*)d_out;

    const int dup = (out_size >= 2 * NUMEL) ? 1 : 0;

    // 1. sub + LayerNorm -> g_xn
    k_subln<<<dim3(NN / 32, BB), dim3(32, 8)>>>(vi, ir, ln_g, ln_b);
    // 2. QKV GEMM: g_qkv = w_qkv @ g_xn    (M=768)
    k_gemm<0><<<dim3(NN / 128, MQKV / 128, BB), 256>>>(w_qkv, nullptr, nullptr, nullptr);
    // 3. dilated local attention -> g_xn (reuse)
    k_attn<<<dim3(NN / 128, 8, BB), 128>>>();
    // 4. proj GEMM + bias + residual: g_div = proj_w @ attn_out + b + (vi - ir)
    k_gemm<1><<<dim3(NN / 128, CC / 128, BB), 256>>>(proj_w, proj_b, vi, ir);
    // 5. batched 64x64 matmul: out = vi @ g_div, duplicated
    k_final<<<BB * CC, 256>>>(vi, out, dup);
}

// round 12
// speedup vs baseline: 1.6401x; 1.6401x over previous
#include <cuda_runtime.h>
#include <cuda_bf16.h>
#include <math.h>
#include <stdint.h>

// Problem constants
#define BB   8
#define CC   256
#define NN   4096          // H*W
#define PP   32768         // B*N fused pixel index
#define NUMEL (BB*CC*NN)   // 8388608

__constant__ int c_dil[4] = {1, 2, 3, 4};
constexpr float SCALE_F = 0.17677669529663687f; // 32^-0.5
constexpr float EPS_F   = 1e-5f;

// ---------------------------------------------------------------------------
// Static device scratch (no runtime allocation)
// ---------------------------------------------------------------------------
// bf16-split operands, K-major transposed: [p][k], p in [0,32768), k in [0,256)
__device__ __align__(16) __nv_bfloat16 g_xh[PP * 256];
__device__ __align__(16) __nv_bfloat16 g_xl[PP * 256];
__device__ __align__(16) __nv_bfloat16 g_yh[PP * 256];
__device__ __align__(16) __nv_bfloat16 g_yl[PP * 256];
// weights split: rows 0..767 = w_qkv, rows 768..1023 = proj_w. [m][k]
__device__ __align__(16) __nv_bfloat16 g_wh[1024 * 256];
__device__ __align__(16) __nv_bfloat16 g_wl[1024 * 256];
// GEMM outputs, fp32, [m][p]
__device__ __align__(16) float g_qkv[768 * PP];
__device__ __align__(16) float g_div[256 * PP];

// ---------------------------------------------------------------------------
// PTX helpers (sm_103-safe: no 'a'-only features)
// ---------------------------------------------------------------------------
__device__ __forceinline__ uint32_t cvta_smem(const void* p) {
    uint32_t a;
    asm("{ .reg .u64 t; cvta.to.shared.u64 t, %1; cvt.u32.u64 %0, t; }"
        : "=r"(a) : "l"(p));
    return a;
}

#define LDM4(r, a) \
    asm volatile("ldmatrix.sync.aligned.m8n8.x4.shared.b16 {%0,%1,%2,%3}, [%4];" \
        : "=r"((r)[0]), "=r"((r)[1]), "=r"((r)[2]), "=r"((r)[3]) : "r"(a))

#define MMA_BF16(c, a, b0_, b1_) \
    asm volatile("mma.sync.aligned.m16n8k16.row.col.f32.bf16.bf16.f32 " \
        "{%0,%1,%2,%3}, {%4,%5,%6,%7}, {%8,%9}, {%0,%1,%2,%3};" \
        : "+f"((c)[0]), "+f"((c)[1]), "+f"((c)[2]), "+f"((c)[3]) \
        : "r"((a)[0]), "r"((a)[1]), "r"((a)[2]), "r"((a)[3]), "r"(b0_), "r"(b1_))

#define CP_ASYNC16(sa, gp) \
    asm volatile("{ .reg .u64 ga; cvta.to.global.u64 ga, %1; " \
                 "cp.async.cg.shared.global [%0], [ga], 16; }" \
        :: "r"(sa), "l"(gp) : "memory")

#define CP_COMMIT() asm volatile("cp.async.commit_group;" ::: "memory")

__device__ __forceinline__ uint32_t pk2(float a, float b) {
    __nv_bfloat162 h = __floats2bfloat162_rn(a, b);
    return *reinterpret_cast<uint32_t*>(&h);
}

// ---------------------------------------------------------------------------
// Kernel W-split: bf16 hi/lo of [w_qkv ; proj_w] (1024 x 256)
// ---------------------------------------------------------------------------
__global__ __launch_bounds__(256)
void k_wsplit(const float* __restrict__ wq, const float* __restrict__ pw)
{
    const int i = blockIdx.x * 256 + threadIdx.x;
    if (i >= 1024 * 256) return;
    const float v = (i < 768 * 256) ? wq[i] : pw[i - 768 * 256];
    const __nv_bfloat16 h = __float2bfloat16(v);
    g_wh[i] = h;
    g_wl[i] = __float2bfloat16(v - __bfloat162float(h));
}

// ---------------------------------------------------------------------------
// Kernel 1: sub + LayerNorm over C, emitting bf16 hi/lo TRANSPOSED: Xt[p][k].
// ---------------------------------------------------------------------------
__global__ __launch_bounds__(256)
void k_subln(const float* __restrict__ vi, const float* __restrict__ ir,
             const float* __restrict__ ln_g, const float* __restrict__ ln_b)
{
    const int b    = blockIdx.y;
    const int pix0 = blockIdx.x * 32;
    const int tx = threadIdx.x, ty = threadIdx.y;
    const int n  = pix0 + tx;
    const size_t base = (size_t)b * CC * NN + n;

    __shared__ float s_t[32 * 257];           // [pixel][channel]
    __shared__ float s_sum[8][32], s_sq[8][32];
    __shared__ float s_mean[32], s_rstd[32];

    float vals[32];
    float s = 0.f, s2 = 0.f;
#pragma unroll
    for (int u = 0; u < 32; ++u) {
        const int c = ty + u * 8;
        const float v = vi[base + (size_t)c * NN] - ir[base + (size_t)c * NN];
        vals[u] = v; s += v; s2 += v * v;
    }
    s_sum[ty][tx] = s; s_sq[ty][tx] = s2;
    __syncthreads();
    if (ty == 0) {
        float tot = 0.f, tot2 = 0.f;
#pragma unroll
        for (int u = 0; u < 8; ++u) { tot += s_sum[u][tx]; tot2 += s_sq[u][tx]; }
        const float mean = tot * (1.0f / CC);
        const float var  = tot2 * (1.0f / CC) - mean * mean;
        s_mean[tx] = mean;
        s_rstd[tx] = rsqrtf(var + EPS_F);
    }
    __syncthreads();
    const float mean = s_mean[tx], rstd = s_rstd[tx];
#pragma unroll
    for (int u = 0; u < 32; ++u) {
        const int c = ty + u * 8;
        s_t[tx * 257 + c] = (vals[u] - mean) * rstd * ln_g[c] + ln_b[c];
    }
    __syncthreads();

    // transposed, coalesced bf16 hi/lo emission
    const int tt = ty * 32 + tx;
    const int pl = tt >> 3;
    const int c0 = (tt & 7) * 32;
    const size_t p = (size_t)b * NN + pix0 + pl;
    const float* row = &s_t[pl * 257 + c0];
    uint4* dh = reinterpret_cast<uint4*>(g_xh + p * 256 + c0);
    uint4* dl = reinterpret_cast<uint4*>(g_xl + p * 256 + c0);
#pragma unroll
    for (int q = 0; q < 4; ++q) {
        uint32_t hx[4], lx[4];
#pragma unroll
        for (int e = 0; e < 4; ++e) {
            const float f0 = row[q * 8 + e * 2];
            const float f1 = row[q * 8 + e * 2 + 1];
            const float h0 = __bfloat162float(__float2bfloat16(f0));
            const float h1 = __bfloat162float(__float2bfloat16(f1));
            hx[e] = pk2(f0, f1);
            lx[e] = pk2(f0 - h0, f1 - h1);
        }
        dh[q] = make_uint4(hx[0], hx[1], hx[2], hx[3]);
        dl[q] = make_uint4(lx[0], lx[1], lx[2], lx[3]);
    }
}

// ---------------------------------------------------------------------------
// HMMA bf16-split GEMM: C[m][p] = sum_k A[m][k] * X[k][p], K=256.
// CTA tile 128x128, BK=32, 256 threads (8 warps, 4m x 2n), warp tile 32x64.
// 3-term split: C = Ah*Bh + Al*Bh + Ah*Bl (fp32 accumulate).
// cp.async double-buffered smem: 2 stages x 4 tiles x (128 rows x 80B).
// MODE 0: A rows 0..767  (w_qkv), B = Xt,  C = g_qkv
// MODE 1: A rows 768..1023 (proj), B = Yt, C = g_div, epi += bias + vi - ir
// ---------------------------------------------------------------------------
#define TILE_B   10240     // 128 rows * 80 B
#define STAGE_B  40960     // 4 tiles
template <int MODE>
__global__ __launch_bounds__(256, 1)
void k_gemm_mma(const float* __restrict__ bias,
                const float* __restrict__ vi,
                const float* __restrict__ ir)
{
    extern __shared__ char smem[];
    const uint32_t sb = cvta_smem(smem);
    const int t    = threadIdx.x;
    const int lane = t & 31, wid = t >> 5;
    const int p0 = blockIdx.x * 128;
    const int m0 = blockIdx.y * 128;
    const int arow0 = (MODE == 0 ? 0 : 768) + m0;

    const __nv_bfloat16* __restrict__ Bh = (MODE == 0 ? g_xh : g_yh);
    const __nv_bfloat16* __restrict__ Bl = (MODE == 0 ? g_xl : g_yl);
    float* __restrict__ Cp = (MODE == 0 ? g_qkv : g_div);

    // ---- global->smem load mapping: 4 tau groups of 64 threads ----
    const int tau = t >> 6, sub = t & 63;
    const __nv_bfloat16* __restrict__ gsrc =
        (tau == 0) ? g_wh + (size_t)arow0 * 256 :
        (tau == 1) ? g_wl + (size_t)arow0 * 256 :
        (tau == 2) ? Bh + (size_t)p0 * 256 :
                     Bl + (size_t)p0 * 256;
    const uint32_t s_tile = sb + tau * TILE_B;

    // ---- fragment lane constants ----
    const int matq = lane >> 3, l7 = lane & 7;
    const int aRow = ((matq & 1) << 3) + l7;      // row within 16
    const int aK   = (matq >> 1) << 3;            // k within 16
    const int bRow = ((matq >> 1) << 3) + l7;
    const int bK   = (matq & 1) << 3;
    const int warp_m = wid >> 1, warp_n = wid & 1;
    const int mb = warp_m * 32, nb = warp_n * 64;
    const uint32_t aOffB = (uint32_t)(mb + aRow) * 80 + aK * 2;
    const uint32_t bOffB = (uint32_t)(nb + bRow) * 80 + bK * 2;

    float acc[2][8][4] = {};

    // ---- prologue: issue chunk 0 ----
    {
        const uint32_t sdst0 = s_tile;
#pragma unroll
        for (int it = 0; it < 8; ++it) {
            const int seg = sub + it * 64;
            const int row = seg >> 2, ks = seg & 3;
            const __nv_bfloat16* gp = gsrc + (size_t)row * 256 + ks * 8;
            CP_ASYNC16(sdst0 + row * 80 + ks * 16, gp);
        }
        CP_COMMIT();
    }

    for (int ch = 0; ch < 8; ++ch) {
        if (ch < 7) {
            const int kc = (ch + 1) * 32;
            const uint32_t sdst0 = s_tile + ((ch + 1) & 1) * STAGE_B;
#pragma unroll
            for (int it = 0; it < 8; ++it) {
                const int seg = sub + it * 64;
                const int row = seg >> 2, ks = seg & 3;
                const __nv_bfloat16* gp = gsrc + (size_t)row * 256 + kc + ks * 8;
                CP_ASYNC16(sdst0 + row * 80 + ks * 16, gp);
            }
            CP_COMMIT();
            asm volatile("cp.async.wait_group 1;" ::: "memory");
        } else {
            asm volatile("cp.async.wait_group 0;" ::: "memory");
        }
        __syncthreads();

        const uint32_t st = sb + (ch & 1) * STAGE_B;
#pragma unroll
        for (int kk2 = 0; kk2 < 2; ++kk2) {
            const uint32_t kB = kk2 * 32;        // 16 bf16 = 32 bytes
            uint32_t ah[2][4], al[2][4], bh[4][4], bl[4][4];
#pragma unroll
            for (int i = 0; i < 2; ++i) {
                LDM4(ah[i], st + 0 * TILE_B + aOffB + i * 1280 + kB);
                LDM4(al[i], st + 1 * TILE_B + aOffB + i * 1280 + kB);
            }
#pragma unroll
            for (int j = 0; j < 4; ++j) {
                LDM4(bh[j], st + 2 * TILE_B + bOffB + j * 1280 + kB);
                LDM4(bl[j], st + 3 * TILE_B + bOffB + j * 1280 + kB);
            }
#pragma unroll
            for (int i = 0; i < 2; ++i)
#pragma unroll
                for (int j = 0; j < 4; ++j)
#pragma unroll
                    for (int h = 0; h < 2; ++h) {
                        const int jn = j * 2 + h;
                        MMA_BF16(acc[i][jn], ah[i], bh[j][h*2], bh[j][h*2+1]);
                        MMA_BF16(acc[i][jn], al[i], bh[j][h*2], bh[j][h*2+1]);
                        MMA_BF16(acc[i][jn], ah[i], bl[j][h*2], bl[j][h*2+1]);
                    }
        }
        __syncthreads();
    }

    // ---- epilogue ----
    const int g  = lane >> 2, tg = lane & 3;
    const int b  = p0 >> 12;          // N tile lies within one batch image
    const int n0 = p0 & 4095;
#pragma unroll
    for (int i = 0; i < 2; ++i) {
#pragma unroll
        for (int r = 0; r < 2; ++r) {
            const int m = m0 + mb + i * 16 + r * 8 + g;
            float* crow = Cp + (size_t)m * PP + p0;
            const float bb = (MODE == 1) ? bias[m] : 0.f;
            const float* vrow = vi + ((size_t)b * CC + m) * NN + n0;
            const float* irow = ir + ((size_t)b * CC + m) * NN + n0;
#pragma unroll
            for (int jn = 0; jn < 8; ++jn) {
                const int col = nb + jn * 8 + tg * 2;
                float2 v = make_float2(acc[i][jn][r*2], acc[i][jn][r*2+1]);
                if (MODE == 1) {
                    const float2 rv = *reinterpret_cast<const float2*>(vrow + col);
                    const float2 ri = *reinterpret_cast<const float2*>(irow + col);
                    v.x += bb + rv.x - ri.x;
                    v.y += bb + rv.y - ri.y;
                }
                *reinterpret_cast<float2*>(crow + col) = v;
            }
        }
    }
}

// ---------------------------------------------------------------------------
// Kernel 3: dilated local attention. One thread per (b, head, pixel).
// Reads g_qkv [o][p] fp32; writes bf16 hi/lo transposed Yt[p][k].
// ---------------------------------------------------------------------------
__global__ __launch_bounds__(128)
void k_attn()
{
    const int b  = blockIdx.z;
    const int hg = blockIdx.y;               // global head 0..7
    const int n  = blockIdx.x * 128 + threadIdx.x;
    const int g  = hg >> 1;                  // dilation group
    const int dil = c_dil[g];
    const int qc = g * 64 + (hg & 1) * 32;   // channel base within 256

    const float* __restrict__ qp = g_qkv + (size_t)qc * PP + (size_t)b * NN;
    const float* __restrict__ kp = g_qkv + (size_t)(256 + qc) * PP + (size_t)b * NN;
    const float* __restrict__ vp = g_qkv + (size_t)(512 + qc) * PP + (size_t)b * NN;

    const int yy = n >> 6, xx = n & 63;

    float q[32];
#pragma unroll
    for (int c = 0; c < 32; ++c) q[c] = qp[(size_t)c * PP + n];

    float logit[9];
    float mx = -1e30f;
#pragma unroll
    for (int t = 0; t < 9; ++t) {
        const int py = yy + (t / 3 - 1) * dil;
        const int px = xx + (t % 3 - 1) * dil;
        float s = 0.f;
        if ((unsigned)py < 64u && (unsigned)px < 64u) {
            const float* kcol = kp + py * 64 + px;
#pragma unroll
            for (int c = 0; c < 32; ++c) s += q[c] * kcol[(size_t)c * PP];
        }
        s *= SCALE_F;           // zero-padded taps give exactly 0 (matches Unfold)
        logit[t] = s;
        mx = fmaxf(mx, s);
    }
    float den = 0.f;
#pragma unroll
    for (int t = 0; t < 9; ++t) { logit[t] = expf(logit[t] - mx); den += logit[t]; }
    const float inv = 1.0f / den;

    float acc[32] = {};
#pragma unroll
    for (int t = 0; t < 9; ++t) {
        const int py = yy + (t / 3 - 1) * dil;
        const int px = xx + (t % 3 - 1) * dil;
        if ((unsigned)py < 64u && (unsigned)px < 64u) {
            const float p = logit[t] * inv;
            const float* vcol = vp + py * 64 + px;
#pragma unroll
            for (int c = 0; c < 32; ++c) acc[c] += p * vcol[(size_t)c * PP];
        }
    }

    // bf16 hi/lo, transposed out: Yt[p][qc..qc+31]
    const size_t p = (size_t)b * NN + n;
    uint4* dh = reinterpret_cast<uint4*>(g_yh + p * 256 + qc);
    uint4* dl = reinterpret_cast<uint4*>(g_yl + p * 256 + qc);
#pragma unroll
    for (int qd = 0; qd < 4; ++qd) {
        uint32_t hx[4], lx[4];
#pragma unroll
        for (int e = 0; e < 4; ++e) {
            const float f0 = acc[qd * 8 + e * 2];
            const float f1 = acc[qd * 8 + e * 2 + 1];
            const float h0 = __bfloat162float(__float2bfloat16(f0));
            const float h1 = __bfloat162float(__float2bfloat16(f1));
            hx[e] = pk2(f0, f1);
            lx[e] = pk2(f0 - h0, f1 - h1);
        }
        dh[qd] = make_uint4(hx[0], hx[1], hx[2], hx[3]);
        dl[qd] = make_uint4(lx[0], lx[1], lx[2], lx[3]);
    }
}

// ---------------------------------------------------------------------------
// Kernel 5: per-(b,c) 64x64 @ 64x64 matmul: o = vi[b,c] @ div[b,c].
// g_div layout is [c][b*4096 + n].
// ---------------------------------------------------------------------------
__global__ __launch_bounds__(256)
void k_final(const float* __restrict__ vi, float* __restrict__ out, int dup)
{
    const int bc = blockIdx.x;
    const int b = bc >> 8, c = bc & 255;
    const float* __restrict__ Ap = vi    + (size_t)bc * 4096;
    const float* __restrict__ Bp = g_div + (size_t)c * PP + (size_t)b * NN;

    __shared__ __align__(16) float Asm[64][68];  // transposed
    __shared__ __align__(16) float Bsm[64][64];

    const int t  = threadIdx.x;
    const int tx = t & 15, ty = t >> 4;

#pragma unroll
    for (int it = 0; it < 4; ++it) {
        const int e  = t + 256 * it;
        const int r  = e >> 4;
        const int c4 = (e & 15) * 4;
        const float4 a4 = *reinterpret_cast<const float4*>(Ap + r * 64 + c4);
        Asm[c4 + 0][r] = a4.x; Asm[c4 + 1][r] = a4.y;
        Asm[c4 + 2][r] = a4.z; Asm[c4 + 3][r] = a4.w;
        *reinterpret_cast<float4*>(&Bsm[r][c4]) =
            *reinterpret_cast<const float4*>(Bp + r * 64 + c4);
    }
    __syncthreads();

    float acc[4][4] = {};
#pragma unroll
    for (int k = 0; k < 64; ++k) {
        float a_[4], b_[4];
#pragma unroll
        for (int i = 0; i < 4; ++i) a_[i] = Asm[k][ty * 4 + i];
#pragma unroll
        for (int j = 0; j < 4; ++j) b_[j] = Bsm[k][tx * 4 + j];
#pragma unroll
        for (int i = 0; i < 4; ++i)
#pragma unroll
            for (int j = 0; j < 4; ++j)
                acc[i][j] += a_[i] * b_[j];
    }

#pragma unroll
    for (int i = 0; i < 4; ++i) {
        const size_t idx = (size_t)bc * 4096 + (size_t)(ty * 4 + i) * 64 + tx * 4;
        const float4 v = make_float4(acc[i][0], acc[i][1], acc[i][2], acc[i][3]);
        *reinterpret_cast<float4*>(out + idx) = v;
        if (dup) *reinterpret_cast<float4*>(out + (size_t)NUMEL + idx) = v;
    }
}

// ---------------------------------------------------------------------------
extern "C" void kernel_launch(void* const* d_in, const int* in_sizes, int n_in,
                              void* d_out, int out_size)
{
    const float* vi     = (const float*)d_in[0];
    const float* ir     = (const float*)d_in[1];
    const float* w_qkv  = (const float*)d_in[2];
    const float* proj_w = (const float*)d_in[3];
    const float* proj_b = (const float*)d_in[4];
    const float* ln_g   = (const float*)d_in[5];
    const float* ln_b   = (const float*)d_in[6];
    float* out = (float*)d_out;

    const int dup = (out_size >= 2 * NUMEL) ? 1 : 0;
    const int SMEM_GEMM = 2 * STAGE_B;   // 81920 B

    static bool attr_done = false;
    if (!attr_done) {
        cudaFuncSetAttribute(k_gemm_mma<0>, cudaFuncAttributeMaxDynamicSharedMemorySize, SMEM_GEMM);
        cudaFuncSetAttribute(k_gemm_mma<1>, cudaFuncAttributeMaxDynamicSharedMemorySize, SMEM_GEMM);
        attr_done = true;
    }

    // 0. weight bf16 split
    k_wsplit<<<1024, 256>>>(w_qkv, proj_w);
    // 1. sub + LN -> Xt hi/lo (transposed bf16 split)
    k_subln<<<dim3(NN / 32, BB), dim3(32, 8)>>>(vi, ir, ln_g, ln_b);
    // 2. QKV GEMM (HMMA): g_qkv[768][32768]
    k_gemm_mma<0><<<dim3(PP / 128, 6), 256, SMEM_GEMM>>>(nullptr, nullptr, nullptr);
    // 3. dilated local attention -> Yt hi/lo
    k_attn<<<dim3(NN / 128, 8, BB), 128>>>();
    // 4. proj GEMM (HMMA) + bias + residual -> g_div[256][32768]
    k_gemm_mma<1><<<dim3(PP / 128, 2), 256, SMEM_GEMM>>>(proj_b, vi, ir);
    // 5. batched 64x64 matmul: out = vi @ div, duplicated
    k_final<<<BB * CC, 256>>>(vi, out, dup);
}